// round 13
// baseline (speedup 1.0000x reference)
#include <cuda_runtime.h>
#include <cuda_fp16.h>
#include <cstdint>
#include <cmath>

// Problem constants
#define B_ 8
#define T_ 4096
#define E_ 512
#define H_ 8
#define D_ 64
#define M_ (B_*T_)   // 32768

#define NCHUNK 64    // pool chunks (64 t each)

// ---------------------------------------------------------------------------
// Scratch (__device__ globals per allocation-free rule)
// ---------------------------------------------------------------------------
__device__ float g_scores[(size_t)M_ * H_];          // 1 MB
__device__ float g_w[B_ * H_ * T_];                  // softmax weights, 1 MB
__device__ float g_partial[NCHUNK * B_ * H_ * E_];   // pool partials, 8 MB
__device__ float g_qf[B_ * E_];                      // q_flat
__device__ float g_kf[B_ * E_];                      // k_flat
__device__ float g_Cq[E_ * H_];                      // Wq@Waq
__device__ float g_cq[H_];
__device__ float g_Ck[B_ * E_ * H_];                 // per-batch Wk@diag(qf)@Wak
__device__ float g_ck[B_ * H_];
__device__ float g_cb[B_ * E_];                      // final bias per batch
__device__ __half g_ah[(size_t)M_ * E_];             // 32 MB  x (fp16)
__device__ __half g_mt[B_ * E_ * E_];                // 4 MB   M^T per batch, fp16
__device__ __half g_wakt[B_ * E_ * E_];              // 4 MB   Wo^T*kf per batch, fp16
__device__ __half g_wqh[E_ * E_];                    // 0.5 MB Wq fp16 (row-major)

// ---------------------------------------------------------------------------
// HMMA / async helpers
// ---------------------------------------------------------------------------
__device__ __forceinline__ uint32_t smem_u32(const void* p) {
    uint32_t a;
    asm("{ .reg .u64 t; cvta.to.shared.u64 t, %1; cvt.u32.u64 %0, t; }" : "=r"(a) : "l"(p));
    return a;
}
__device__ __forceinline__ void ldm_x4(uint32_t& r0, uint32_t& r1, uint32_t& r2, uint32_t& r3,
                                       uint32_t addr) {
    asm volatile("ldmatrix.sync.aligned.m8n8.x4.shared.b16 {%0,%1,%2,%3}, [%4];"
                 : "=r"(r0), "=r"(r1), "=r"(r2), "=r"(r3) : "r"(addr));
}
__device__ __forceinline__ void mma16816(float* c, const uint32_t* a, const uint32_t* b) {
    asm volatile(
        "mma.sync.aligned.m16n8k16.row.col.f32.f16.f16.f32 "
        "{%0,%1,%2,%3}, {%4,%5,%6,%7}, {%8,%9}, {%0,%1,%2,%3};"
        : "+f"(c[0]), "+f"(c[1]), "+f"(c[2]), "+f"(c[3])
        : "r"(a[0]), "r"(a[1]), "r"(a[2]), "r"(a[3]), "r"(b[0]), "r"(b[1]));
}
__device__ __forceinline__ void cp16(uint32_t saddr, const void* gaddr) {
    asm volatile("cp.async.cg.shared.global [%0], [%1], 16;" :: "r"(saddr), "l"(gaddr));
}
#define CP_COMMIT() asm volatile("cp.async.commit_group;" ::: "memory")
#define CP_WAIT(n)  asm volatile("cp.async.wait_group %0;" :: "n"(n) : "memory")

// ---------------------------------------------------------------------------
// Final HMMA GEMM, single fp16 segment, cp.async 3-stage pipeline, BK=64.
// ---------------------------------------------------------------------------
#define LDT    40                 // padded stride (halves) for buildM (BK=32)
#define LDT64  72                 // padded stride (halves) for BK=64 (144B rows)
#define TILE64H (128 * LDT64)     // 9216 halves
#define STAGE64H (2 * TILE64H)    // A + B per stage
#define NSTAGE 3
#define GEMM_SMEM (NSTAGE * STAGE64H * 2)   // 110592 bytes

__global__ __launch_bounds__(256, 2)
void hmma_gemm_fused(const __half* __restrict__ A0,
                     const __half* __restrict__ Bt,
                     const float* __restrict__ bias, float* __restrict__ C)
{
    extern __shared__ __half smem[];

    const int tid  = threadIdx.x;
    const int wid  = tid >> 5;
    const int lane = tid & 31;
    const int wm   = wid & 1;
    const int wn   = wid >> 1;
    const int row0 = blockIdx.y * 128;
    const int col0 = blockIdx.x * 128;
    const int b    = row0 / T_;

    const __half* Btb = Bt + (size_t)b * E_ * E_;
    const float* bias_b = bias + b * E_;
    const uint32_t sbase = smem_u32(smem);

    float acc[4][4][4];
    #pragma unroll
    for (int i = 0; i < 4; i++)
        #pragma unroll
        for (int j = 0; j < 4; j++)
            #pragma unroll
            for (int u = 0; u < 4; u++) acc[i][j][u] = 0.f;

    auto issue = [&](int s) {
        const int k0 = s * 64;
        const uint32_t st = sbase + (uint32_t)((s % NSTAGE) * STAGE64H) * 2;
        #pragma unroll
        for (int j = 0; j < 4; j++) {
            const int c = tid + 256 * j;
            const int r = c >> 3, kg = c & 7;
            const uint32_t off = (uint32_t)(r * LDT64 + kg * 8) * 2;
            cp16(st + off,                A0  + (size_t)(row0 + r) * E_ + k0 + kg * 8);
            cp16(st + TILE64H * 2 + off,  Btb + (size_t)(col0 + r) * E_ + k0 + kg * 8);
        }
        CP_COMMIT();
    };

    issue(0);
    issue(1);

    const int r   = lane & 7;
    const int sel = lane >> 3;

    for (int i = 0; i < 8; i++) {
        CP_WAIT(1);
        __syncthreads();

        if (i + 2 < 8) issue(i + 2);

        const uint32_t st = sbase + (uint32_t)((i % NSTAGE) * STAGE64H) * 2;
        const uint32_t a_base = st;
        const uint32_t b_base = st + TILE64H * 2;

        #pragma unroll
        for (int ks = 0; ks < 4; ks++) {
            const int k = ks * 16;
            uint32_t bfr[4][2];
            #pragma unroll
            for (int p = 0; p < 2; p++) {
                uint32_t addr = b_base +
                    (uint32_t)((wn * 32 + p * 16 + r + (sel >> 1) * 8) * LDT64 + k + (sel & 1) * 8) * 2;
                ldm_x4(bfr[2 * p][0], bfr[2 * p][1], bfr[2 * p + 1][0], bfr[2 * p + 1][1], addr);
            }
            const uint32_t a_off = a_base +
                (uint32_t)((wm * 64 + r + (sel & 1) * 8) * LDT64 + k + (sel >> 1) * 8) * 2;
            #pragma unroll
            for (int mt = 0; mt < 4; mt++) {
                uint32_t af[4];
                ldm_x4(af[0], af[1], af[2], af[3], a_off + (uint32_t)(mt * 16 * LDT64) * 2);
                #pragma unroll
                for (int nt = 0; nt < 4; nt++)
                    mma16816(acc[mt][nt], af, bfr[nt]);
            }
        }
    }

    #pragma unroll
    for (int mt = 0; mt < 4; mt++) {
        const int mg = row0 + wm * 64 + mt * 16 + (lane >> 2);
        #pragma unroll
        for (int nt = 0; nt < 4; nt++) {
            const int ng = col0 + wn * 32 + nt * 8 + (lane & 3) * 2;
            const float bi0 = bias_b[ng], bi1 = bias_b[ng + 1];
            *reinterpret_cast<float2*>(C + (size_t)mg * E_ + ng) =
                make_float2(acc[mt][nt][0] + bi0, acc[mt][nt][1] + bi1);
            *reinterpret_cast<float2*>(C + (size_t)(mg + 8) * E_ + ng) =
                make_float2(acc[mt][nt][2] + bi0, acc[mt][nt][3] + bi1);
        }
    }
}

// ---------------------------------------------------------------------------
// buildM HMMA: mt[m=b*512+n][e1] = fp16( sum_e2 wakt[m][e2]*wqh[e1][e2] + Wq[e1][n] )
// ---------------------------------------------------------------------------
__global__ __launch_bounds__(256, 2)
void hmma_buildM(const __half* __restrict__ A0, const __half* __restrict__ Bt,
                 const float* __restrict__ Wq, __half* __restrict__ Cmt)
{
    __shared__ __align__(16) __half As[2][128 * LDT];
    __shared__ __align__(16) __half Bs[2][128 * LDT];

    const int tid  = threadIdx.x;
    const int wid  = tid >> 5;
    const int lane = tid & 31;
    const int wm   = wid & 1;
    const int wn   = wid >> 1;
    const int row0 = blockIdx.y * 128;
    const int col0 = blockIdx.x * 128;

    const int lrow  = tid & 127;
    const int lhalf = tid >> 7;

    float acc[4][4][4];
    #pragma unroll
    for (int i = 0; i < 4; i++)
        #pragma unroll
        for (int j = 0; j < 4; j++)
            #pragma unroll
            for (int u = 0; u < 4; u++) acc[i][j][u] = 0.f;

    uint4 ar0, ar1, br0, br1;
    {
        const __half* ga = A0 + (size_t)(row0 + lrow) * E_ + lhalf * 16;
        const __half* gb = Bt + (size_t)(col0 + lrow) * E_ + lhalf * 16;
        ar0 = reinterpret_cast<const uint4*>(ga)[0];
        ar1 = reinterpret_cast<const uint4*>(ga)[1];
        br0 = reinterpret_cast<const uint4*>(gb)[0];
        br1 = reinterpret_cast<const uint4*>(gb)[1];
        __half* sa = &As[0][lrow * LDT + lhalf * 16];
        __half* sb = &Bs[0][lrow * LDT + lhalf * 16];
        reinterpret_cast<uint4*>(sa)[0] = ar0;
        reinterpret_cast<uint4*>(sa)[1] = ar1;
        reinterpret_cast<uint4*>(sb)[0] = br0;
        reinterpret_cast<uint4*>(sb)[1] = br1;
    }
    __syncthreads();

    const int r   = lane & 7;
    const int sel = lane >> 3;

    for (int i = 0; i < 16; i++) {
        const int buf = i & 1;
        if (i + 1 < 16) {
            const int k0 = (i + 1) * 32;
            const __half* ga = A0 + (size_t)(row0 + lrow) * E_ + k0 + lhalf * 16;
            const __half* gb = Bt + (size_t)(col0 + lrow) * E_ + k0 + lhalf * 16;
            ar0 = reinterpret_cast<const uint4*>(ga)[0];
            ar1 = reinterpret_cast<const uint4*>(ga)[1];
            br0 = reinterpret_cast<const uint4*>(gb)[0];
            br1 = reinterpret_cast<const uint4*>(gb)[1];
        }

        const uint32_t abase = smem_u32(&As[buf][0]);
        const uint32_t bbase = smem_u32(&Bs[buf][0]);
        #pragma unroll
        for (int ks = 0; ks < 2; ks++) {
            const int k = ks * 16;
            uint32_t bfr[4][2];
            #pragma unroll
            for (int p = 0; p < 2; p++) {
                uint32_t addr = bbase +
                    (uint32_t)((wn * 32 + p * 16 + r + (sel >> 1) * 8) * LDT + k + (sel & 1) * 8) * 2;
                ldm_x4(bfr[2 * p][0], bfr[2 * p][1], bfr[2 * p + 1][0], bfr[2 * p + 1][1], addr);
            }
            #pragma unroll
            for (int mt = 0; mt < 4; mt++) {
                uint32_t af[4];
                uint32_t addr = abase +
                    (uint32_t)((wm * 64 + mt * 16 + r + (sel & 1) * 8) * LDT + k + (sel >> 1) * 8) * 2;
                ldm_x4(af[0], af[1], af[2], af[3], addr);
                #pragma unroll
                for (int nt = 0; nt < 4; nt++)
                    mma16816(acc[mt][nt], af, bfr[nt]);
            }
        }

        if (i + 1 < 16) {
            const int nb = (i + 1) & 1;
            __half* sa = &As[nb][lrow * LDT + lhalf * 16];
            __half* sb = &Bs[nb][lrow * LDT + lhalf * 16];
            reinterpret_cast<uint4*>(sa)[0] = ar0;
            reinterpret_cast<uint4*>(sa)[1] = ar1;
            reinterpret_cast<uint4*>(sb)[0] = br0;
            reinterpret_cast<uint4*>(sb)[1] = br1;
            __syncthreads();
        }
    }

    #pragma unroll
    for (int mt = 0; mt < 4; mt++) {
        const int mg = row0 + wm * 64 + mt * 16 + (lane >> 2);
        const int n  = mg & 511;
        #pragma unroll
        for (int nt = 0; nt < 4; nt++) {
            const int ng = col0 + wn * 32 + nt * 8 + (lane & 3) * 2;
            float v0 = acc[mt][nt][0] + Wq[(size_t)ng * E_ + n];
            float v1 = acc[mt][nt][1] + Wq[(size_t)(ng + 1) * E_ + n];
            float v2 = acc[mt][nt][2] + Wq[(size_t)ng * E_ + n + 8];
            float v3 = acc[mt][nt][3] + Wq[(size_t)(ng + 1) * E_ + n + 8];
            *reinterpret_cast<__half2*>(Cmt + (size_t)mg * E_ + ng) =
                __half2(__float2half(v0), __float2half(v1));
            *reinterpret_cast<__half2*>(Cmt + (size_t)(mg + 8) * E_ + ng) =
                __half2(__float2half(v2), __float2half(v3));
        }
    }
}

// ---------------------------------------------------------------------------
// Fused: wakt = fp16(Wo^T * kf) (y<16); cb bias (y==16)
// ---------------------------------------------------------------------------
__global__ __launch_bounds__(256)
void woTkf_cbias_kernel(const float* __restrict__ Wo, const float* __restrict__ kf,
                        const float* __restrict__ bq, const float* __restrict__ bo,
                        __half* __restrict__ wakt, float* __restrict__ cb)
{
    const int b = blockIdx.z;
    if (blockIdx.y == 16) {
        if (blockIdx.x >= 2) return;
        const int n = blockIdx.x * 256 + threadIdx.x;
        float a = 0.f;
        for (int e = 0; e < E_; e++)
            a = fmaf(bq[e] * kf[b * E_ + e], Wo[(size_t)e * E_ + n], a);
        cb[b * E_ + n] = a + bo[n] + bq[n];
        return;
    }
    __shared__ float t[32][33];
    const int n0 = blockIdx.x * 32, e20 = blockIdx.y * 32;
    const int tx = threadIdx.x & 31, ty = threadIdx.x >> 5;
    #pragma unroll
    for (int j = 0; j < 4; j++) {
        const int e2 = e20 + ty * 4 + j;
        t[ty * 4 + j][tx] = Wo[(size_t)e2 * E_ + n0 + tx] * kf[b * E_ + e2];
    }
    __syncthreads();
    #pragma unroll
    for (int j = 0; j < 4; j++) {
        const int n = n0 + ty * 4 + j;
        wakt[((size_t)b * E_ + n) * E_ + e20 + tx] = __float2half(t[tx][ty * 4 + j]);
    }
}

// ---------------------------------------------------------------------------
// Fused: Cq = Wq@Waq (blocks 0..15); wqh = fp16(Wq) (blocks 16..271)
// ---------------------------------------------------------------------------
__global__ __launch_bounds__(256)
void prep_q_kernel(const float* __restrict__ Wq, const float* __restrict__ Wa,
                   const float* __restrict__ bvec, const float* __restrict__ ba,
                   float* __restrict__ C, float* __restrict__ cv,
                   __half* __restrict__ wqh)
{
    const int tid = threadIdx.x;
    if (blockIdx.x >= 16) {
        const int i = (blockIdx.x - 16) * 256 + tid;
        const float4 v = reinterpret_cast<const float4*>(Wq)[i];
        __half2* hp = reinterpret_cast<__half2*>(wqh) + 2 * i;
        hp[0] = __half2(__float2half(v.x), __float2half(v.y));
        hp[1] = __half2(__float2half(v.z), __float2half(v.w));
        return;
    }
    __shared__ float s[E_][H_];
    for (int i = tid; i < E_ * H_; i += 256) s[i >> 3][i & 7] = Wa[i];
    __syncthreads();
    const int e1 = blockIdx.x * 32 + (tid >> 3);
    const int h  = tid & 7;
    const float* wr = Wq + (size_t)e1 * E_;
    float acc = 0.f;
    for (int e2 = 0; e2 < E_; e2++) acc = fmaf(wr[e2], s[e2][h], acc);
    C[(size_t)e1 * H_ + h] = acc;
    if (blockIdx.x == 0 && tid < H_) {
        float a = 0.f;
        for (int e2 = 0; e2 < E_; e2++) a = fmaf(bvec[e2], s[e2][tid], a);
        cv[tid] = a + ba[tid];
    }
}

// ---------------------------------------------------------------------------
// C[bb][e1][h] = sum_e2 W[e1,e2] * scale[bb,e2] * Wa[e2,h]   (k path)
// ---------------------------------------------------------------------------
__global__ __launch_bounds__(256)
void cmat_kernel(const float* __restrict__ W, const float* __restrict__ Wa,
                 const float* __restrict__ bvec, const float* __restrict__ ba,
                 const float* __restrict__ scale,
                 float* __restrict__ C, float* __restrict__ cv)
{
    const int bb = blockIdx.y;
    __shared__ float s[E_][H_];
    const int tid = threadIdx.x;
    for (int i = tid; i < E_ * H_; i += 256) {
        const int e2 = i >> 3, h = i & 7;
        s[e2][h] = scale[bb * E_ + e2] * Wa[i];
    }
    __syncthreads();
    const int e1 = blockIdx.x * 32 + (tid >> 3);
    const int h  = tid & 7;
    const float* wr = W + (size_t)e1 * E_;
    float acc = 0.f;
    for (int e2 = 0; e2 < E_; e2++) acc = fmaf(wr[e2], s[e2][h], acc);
    C[((size_t)bb * E_ + e1) * H_ + h] = acc;
    if (blockIdx.x == 0 && tid < H_) {
        float a = 0.f;
        for (int e2 = 0; e2 < E_; e2++) a = fmaf(bvec[e2], s[e2][tid], a);
        cv[bb * H_ + tid] = a + ba[tid];
    }
}

// ---------------------------------------------------------------------------
// Fused: convert x -> fp16 (coalesced uint2 stores) AND q_scores = x@Cq + cq
// ---------------------------------------------------------------------------
__global__ __launch_bounds__(256)
void split_scores_kernel(const float* __restrict__ x, __half* __restrict__ ah,
                         const float* __restrict__ Cq, const float* __restrict__ cq,
                         float* __restrict__ S)
{
    __shared__ float wT[H_][E_];
    __shared__ float bsh[H_];
    const int tid = threadIdx.x;
    for (int i = tid; i < E_ * H_; i += 256) wT[i & 7][i >> 3] = Cq[i];
    if (tid < H_) bsh[tid] = cq[tid];
    __syncthreads();

    const int warp = tid >> 5, lane = tid & 31;
    const int m = blockIdx.x * 8 + warp;
    const float4* xr = reinterpret_cast<const float4*>(x + (size_t)m * E_);

    float s[H_] = {0.f, 0.f, 0.f, 0.f, 0.f, 0.f, 0.f, 0.f};
    #pragma unroll
    for (int c = 0; c < 4; c++) {
        const int fi = c * 32 + lane;
        const float4 v = xr[fi];
        const int e = fi * 4;
        #pragma unroll
        for (int h = 0; h < H_; h++)
            s[h] += v.x * wT[h][e] + v.y * wT[h][e + 1] + v.z * wT[h][e + 2] + v.w * wT[h][e + 3];
        const __half2 p0 = __half2(__float2half(v.x), __float2half(v.y));
        const __half2 p1 = __half2(__float2half(v.z), __float2half(v.w));
        uint2 st;
        st.x = *reinterpret_cast<const uint32_t*>(&p0);
        st.y = *reinterpret_cast<const uint32_t*>(&p1);
        *reinterpret_cast<uint2*>(ah + (size_t)m * E_ + e) = st;   // one 8B coalesced store
    }
    #pragma unroll
    for (int off = 16; off; off >>= 1)
        #pragma unroll
        for (int h = 0; h < H_; h++) s[h] += __shfl_xor_sync(0xffffffffu, s[h], off);
    if (lane < H_) S[(size_t)m * H_ + lane] = s[lane] + bsh[lane];
}

// k_scores with per-batch C, reading fp16 x
__global__ __launch_bounds__(256)
void scores_pb_kernel(const __half* __restrict__ xh, const float* __restrict__ C,
                      const float* __restrict__ cv, float* __restrict__ S)
{
    const int b = blockIdx.x >> 9;
    __shared__ float wT[H_][E_];
    __shared__ float bsh[H_];
    const int tid = threadIdx.x;
    const float* Cb = C + (size_t)b * E_ * H_;
    for (int i = tid; i < E_ * H_; i += 256) wT[i & 7][i >> 3] = Cb[i];
    if (tid < H_) bsh[tid] = cv[b * H_ + tid];
    __syncthreads();

    const int warp = tid >> 5, lane = tid & 31;
    const int m = blockIdx.x * 8 + warp;
    const uint4* xr = reinterpret_cast<const uint4*>(xh + (size_t)m * E_);

    float s[H_] = {0.f, 0.f, 0.f, 0.f, 0.f, 0.f, 0.f, 0.f};
    #pragma unroll
    for (int c = 0; c < 2; c++) {
        const int fi = c * 32 + lane;
        const uint4 raw = xr[fi];
        const int e = fi * 8;
        const __half2* p = reinterpret_cast<const __half2*>(&raw);
        #pragma unroll
        for (int j = 0; j < 4; j++) {
            const float2 f = __half22float2(p[j]);
            #pragma unroll
            for (int h = 0; h < H_; h++)
                s[h] += f.x * wT[h][e + 2 * j] + f.y * wT[h][e + 2 * j + 1];
        }
    }
    #pragma unroll
    for (int off = 16; off; off >>= 1)
        #pragma unroll
        for (int h = 0; h < H_; h++) s[h] += __shfl_xor_sync(0xffffffffu, s[h], off);
    if (lane < H_) S[(size_t)m * H_ + lane] = s[lane] + bsh[lane];
}

// ---------------------------------------------------------------------------
// softmax weights per (b,h) — 1024 threads
// ---------------------------------------------------------------------------
__global__ __launch_bounds__(1024)
void softmax_kernel(const float* __restrict__ S, const unsigned char* __restrict__ mask,
                    float* __restrict__ w)
{
    const int bh = blockIdx.x;
    const int b = bh >> 3, h = bh & 7;
    __shared__ float buf[T_];
    __shared__ float red[1024];
    const int tid = threadIdx.x;

    float mx = -INFINITY;
    #pragma unroll
    for (int c = 0; c < 4; c++) {
        const int t = c * 1024 + tid;
        float s = S[((size_t)b * T_ + t) * H_ + h] * 0.125f;
        if (mask[b * T_ + t]) s = -INFINITY;
        buf[t] = s;
        mx = fmaxf(mx, s);
    }
    red[tid] = mx; __syncthreads();
    #pragma unroll
    for (int s2 = 512; s2 > 0; s2 >>= 1) {
        if (tid < s2) red[tid] = fmaxf(red[tid], red[tid + s2]);
        __syncthreads();
    }
    mx = red[0];
    __syncthreads();

    float sum = 0.f;
    #pragma unroll
    for (int c = 0; c < 4; c++) {
        const int t = c * 1024 + tid;
        const float e = expf(buf[t] - mx);
        buf[t] = e;
        sum += e;
    }
    red[tid] = sum; __syncthreads();
    #pragma unroll
    for (int s2 = 512; s2 > 0; s2 >>= 1) {
        if (tid < s2) red[tid] += red[tid + s2];
        __syncthreads();
    }
    const float inv = 1.f / red[0];
    __syncthreads();
    #pragma unroll
    for (int c = 0; c < 4; c++) {
        const int t = c * 1024 + tid;
        w[(size_t)bh * T_ + t] = buf[t] * inv;
    }
}

// ---------------------------------------------------------------------------
// pool fp16 x, v2: uint2 loads (8B/thread), 2 t-rows in flight, unrolled.
// partial[chunk][b][h][e], 64 t per chunk. grid (NCHUNK, B), 256 threads.
// ---------------------------------------------------------------------------
__global__ __launch_bounds__(256)
void pool_x_kernel(const float* __restrict__ w, const __half* __restrict__ xh,
                   float* __restrict__ partial)
{
    const int chunk = blockIdx.x, b = blockIdx.y;
    __shared__ float ws[H_][64];
    __shared__ float red[H_][E_ / 4][4];   // 16 KB, tg=1 partials
    const int tid = threadIdx.x;
    const int eg = tid & 127;              // uint2 index: halves [eg*4, eg*4+4)
    const int tg = tid >> 7;               // 0/1: which t of each pair

    for (int i = tid; i < H_ * 64; i += 256)
        ws[i >> 6][i & 63] = w[(size_t)(b * 8 + (i >> 6)) * T_ + chunk * 64 + (i & 63)];
    __syncthreads();

    float acc[H_][4];
    #pragma unroll
    for (int h = 0; h < H_; h++)
        #pragma unroll
        for (int j = 0; j < 4; j++) acc[h][j] = 0.f;

    const __half* xp = xh + (size_t)b * T_ * E_ + (size_t)chunk * 64 * E_;
    #pragma unroll 4
    for (int it = 0; it < 32; it++) {
        const int tt = it * 2 + tg;
        const uint2 raw = *reinterpret_cast<const uint2*>(xp + (size_t)tt * E_ + eg * 4);
        const __half2 h0 = *reinterpret_cast<const __half2*>(&raw.x);
        const __half2 h1 = *reinterpret_cast<const __half2*>(&raw.y);
        const float2 f0 = __half22float2(h0);
        const float2 f1 = __half22float2(h1);
        #pragma unroll
        for (int h = 0; h < H_; h++) {
            const float wv = ws[h][tt];
            acc[h][0] = fmaf(wv, f0.x, acc[h][0]);
            acc[h][1] = fmaf(wv, f0.y, acc[h][1]);
            acc[h][2] = fmaf(wv, f1.x, acc[h][2]);
            acc[h][3] = fmaf(wv, f1.y, acc[h][3]);
        }
    }

    if (tg == 1) {
        #pragma unroll
        for (int h = 0; h < H_; h++)
            #pragma unroll
            for (int j = 0; j < 4; j++) red[h][eg][j] = acc[h][j];
    }
    __syncthreads();
    if (tg == 0) {
        #pragma unroll
        for (int h = 0; h < H_; h++) {
            float4 o;
            o.x = acc[h][0] + red[h][eg][0];
            o.y = acc[h][1] + red[h][eg][1];
            o.z = acc[h][2] + red[h][eg][2];
            o.w = acc[h][3] + red[h][eg][3];
            *reinterpret_cast<float4*>(
                partial + (((size_t)chunk * 8 + b) * 8 + h) * E_ + eg * 4) = o;
        }
    }
}

// ---------------------------------------------------------------------------
// flat: out[b, h*64+d] = (sum_c partial[c][b][h][:]) @ W[:, h*64+d] + bvec  (*qf)
// ---------------------------------------------------------------------------
template<bool MULQF>
__global__ __launch_bounds__(256)
void flat_kernel(const float* __restrict__ partial, const float* __restrict__ W,
                 const float* __restrict__ bvec, const float* __restrict__ qf_in,
                 float* __restrict__ out)
{
    const int b = blockIdx.x, h = blockIdx.y;
    __shared__ float px[E_];
    __shared__ float red[256];
    const int tid = threadIdx.x;
    for (int e = tid; e < E_; e += 256) {
        float a = 0.f;
        #pragma unroll
        for (int c = 0; c < NCHUNK; c++) a += partial[(((size_t)c * 8 + b) * 8 + h) * E_ + e];
        px[e] = a;
    }
    __syncthreads();
    const int d = tid & 63, q = tid >> 6;
    float acc = 0.f;
    for (int k = q * 128; k < q * 128 + 128; k++)
        acc = fmaf(px[k], W[(size_t)k * E_ + h * D_ + d], acc);
    red[tid] = acc; __syncthreads();
    if (tid < 64) {
        float v = red[tid] + red[tid + 64] + red[tid + 128] + red[tid + 192] + bvec[h * D_ + d];
        if (MULQF) v *= qf_in[b * E_ + h * D_ + d];
        out[b * E_ + h * D_ + d] = v;
    }
}

// ---------------------------------------------------------------------------
// Launch sequence
// ---------------------------------------------------------------------------
extern "C" void kernel_launch(void* const* d_in, const int* in_sizes, int n_in,
                              void* d_out, int out_size)
{
    const float* x            = (const float*)d_in[0];
    const unsigned char* mask = (const unsigned char*)d_in[3];
    const float* Wq  = (const float*)d_in[4];
    const float* bq  = (const float*)d_in[5];
    const float* Waq = (const float*)d_in[6];
    const float* baq = (const float*)d_in[7];
    const float* Wk  = (const float*)d_in[8];
    const float* bk  = (const float*)d_in[9];
    const float* Wak = (const float*)d_in[10];
    const float* bak = (const float*)d_in[11];
    const float* Wo  = (const float*)d_in[12];
    const float* bo  = (const float*)d_in[13];
    float* out = (float*)d_out;

    float *sc_, *w_, *pp_, *qf_, *kf_, *Cq_, *cq_, *Ck_, *ck_, *cb_;
    __half *ah, *mt, *wakt, *wqh;
    cudaGetSymbolAddress((void**)&sc_, g_scores);
    cudaGetSymbolAddress((void**)&w_,  g_w);
    cudaGetSymbolAddress((void**)&pp_, g_partial);
    cudaGetSymbolAddress((void**)&qf_, g_qf);
    cudaGetSymbolAddress((void**)&kf_, g_kf);
    cudaGetSymbolAddress((void**)&Cq_, g_Cq);
    cudaGetSymbolAddress((void**)&cq_, g_cq);
    cudaGetSymbolAddress((void**)&Ck_, g_Ck);
    cudaGetSymbolAddress((void**)&ck_, g_ck);
    cudaGetSymbolAddress((void**)&cb_, g_cb);
    cudaGetSymbolAddress((void**)&ah,  g_ah);
    cudaGetSymbolAddress((void**)&mt,  g_mt);
    cudaGetSymbolAddress((void**)&wakt, g_wakt);
    cudaGetSymbolAddress((void**)&wqh, g_wqh);

    cudaFuncSetAttribute(hmma_gemm_fused, cudaFuncAttributeMaxDynamicSharedMemorySize, GEMM_SMEM);

    // 1) Cq = Wq@Waq + wqh convert (fused); fp16 convert of x + q_scores (fused)
    prep_q_kernel<<<16 + 256, 256>>>(Wq, Waq, bq, baq, Cq_, cq_, wqh);
    split_scores_kernel<<<M_ / 8, 256>>>(x, ah, Cq_, cq_, sc_);
    // 2) q softmax + pool (fp16 x) + q_flat
    softmax_kernel<<<B_ * H_, 1024>>>(sc_, mask, w_);
    pool_x_kernel<<<dim3(NCHUNK, B_), 256>>>(w_, ah, pp_);
    flat_kernel<false><<<dim3(B_, H_), 256>>>(pp_, Wq, bq, nullptr, qf_);
    // 3) per-batch Ck; k_scores from fp16 x
    cmat_kernel<<<dim3(16, B_), 256>>>(Wk, Wak, bk, bak, qf_, Ck_, ck_);
    scores_pb_kernel<<<M_ / 8, 256>>>(ah, Ck_, ck_, sc_);
    // 4) k softmax + pool (fp16 x) + k_flat
    softmax_kernel<<<B_ * H_, 1024>>>(sc_, mask, w_);
    pool_x_kernel<<<dim3(NCHUNK, B_), 256>>>(w_, ah, pp_);
    flat_kernel<true><<<dim3(B_, H_), 256>>>(pp_, Wk, bk, qf_, kf_);
    // 5) M^T via tensor cores (woTkf + cbias fused)
    woTkf_cbias_kernel<<<dim3(16, 17, B_), 256>>>(Wo, kf_, bq, bo, wakt, cb_);
    hmma_buildM<<<dim3(E_ / 128, B_ * E_ / 128), 256>>>(wakt, wqh, Wq, mt);
    // 6) final GEMM: out = x @ M_b + cb_b
    hmma_gemm_fused<<<dim3(E_ / 128, M_ / 128), 256, GEMM_SMEM>>>(ah, mt, cb_, out);
}

// round 14
// speedup vs baseline: 1.0080x; 1.0080x over previous
#include <cuda_runtime.h>
#include <cuda_fp16.h>
#include <cstdint>
#include <cmath>

// Problem constants
#define B_ 8
#define T_ 4096
#define E_ 512
#define H_ 8
#define D_ 64
#define M_ (B_*T_)   // 32768

#define NCHUNK 64    // pool chunks (64 t each)

// ---------------------------------------------------------------------------
// Scratch (__device__ globals per allocation-free rule)
// ---------------------------------------------------------------------------
__device__ float g_scores[(size_t)M_ * H_];          // 1 MB
__device__ float g_w[B_ * H_ * T_];                  // softmax weights, 1 MB
__device__ float g_partial[NCHUNK * B_ * H_ * E_];   // pool partials, 8 MB
__device__ float g_qf[B_ * E_];                      // q_flat
__device__ float g_kf[B_ * E_];                      // k_flat
__device__ float g_Cq[E_ * H_];                      // Wq@Waq
__device__ float g_cq[H_];
__device__ float g_Ck[B_ * E_ * H_];                 // per-batch Wk@diag(qf)@Wak
__device__ float g_ck[B_ * H_];
__device__ float g_cb[B_ * E_];                      // final bias per batch
__device__ __half g_ah[(size_t)M_ * E_];             // 32 MB  x (fp16)
__device__ __half g_mt[B_ * E_ * E_];                // 4 MB   M^T per batch, fp16
__device__ __half g_wakt[B_ * E_ * E_];              // 4 MB   Wo^T*kf per batch, fp16
__device__ __half g_wqh[E_ * E_];                    // 0.5 MB Wq fp16 (row-major)

// ---------------------------------------------------------------------------
// HMMA / async helpers
// ---------------------------------------------------------------------------
__device__ __forceinline__ uint32_t smem_u32(const void* p) {
    uint32_t a;
    asm("{ .reg .u64 t; cvta.to.shared.u64 t, %1; cvt.u32.u64 %0, t; }" : "=r"(a) : "l"(p));
    return a;
}
__device__ __forceinline__ void ldm_x4(uint32_t& r0, uint32_t& r1, uint32_t& r2, uint32_t& r3,
                                       uint32_t addr) {
    asm volatile("ldmatrix.sync.aligned.m8n8.x4.shared.b16 {%0,%1,%2,%3}, [%4];"
                 : "=r"(r0), "=r"(r1), "=r"(r2), "=r"(r3) : "r"(addr));
}
__device__ __forceinline__ void mma16816(float* c, const uint32_t* a, const uint32_t* b) {
    asm volatile(
        "mma.sync.aligned.m16n8k16.row.col.f32.f16.f16.f32 "
        "{%0,%1,%2,%3}, {%4,%5,%6,%7}, {%8,%9}, {%0,%1,%2,%3};"
        : "+f"(c[0]), "+f"(c[1]), "+f"(c[2]), "+f"(c[3])
        : "r"(a[0]), "r"(a[1]), "r"(a[2]), "r"(a[3]), "r"(b[0]), "r"(b[1]));
}
__device__ __forceinline__ void cp16(uint32_t saddr, const void* gaddr) {
    asm volatile("cp.async.cg.shared.global [%0], [%1], 16;" :: "r"(saddr), "l"(gaddr));
}
#define CP_COMMIT() asm volatile("cp.async.commit_group;" ::: "memory")
#define CP_WAIT(n)  asm volatile("cp.async.wait_group %0;" :: "n"(n) : "memory")

// ---------------------------------------------------------------------------
// Final HMMA GEMM, single fp16 segment, cp.async 3-stage pipeline, BK=64.
// ---------------------------------------------------------------------------
#define LDT    40                 // padded stride (halves) for buildM (BK=32)
#define LDT64  72                 // padded stride (halves) for BK=64 (144B rows)
#define TILE64H (128 * LDT64)     // 9216 halves
#define STAGE64H (2 * TILE64H)    // A + B per stage
#define NSTAGE 3
#define GEMM_SMEM (NSTAGE * STAGE64H * 2)   // 110592 bytes

__global__ __launch_bounds__(256, 2)
void hmma_gemm_fused(const __half* __restrict__ A0,
                     const __half* __restrict__ Bt,
                     const float* __restrict__ bias, float* __restrict__ C)
{
    extern __shared__ __half smem[];

    const int tid  = threadIdx.x;
    const int wid  = tid >> 5;
    const int lane = tid & 31;
    const int wm   = wid & 1;
    const int wn   = wid >> 1;
    const int row0 = blockIdx.y * 128;
    const int col0 = blockIdx.x * 128;
    const int b    = row0 / T_;

    const __half* Btb = Bt + (size_t)b * E_ * E_;
    const float* bias_b = bias + b * E_;
    const uint32_t sbase = smem_u32(smem);

    float acc[4][4][4];
    #pragma unroll
    for (int i = 0; i < 4; i++)
        #pragma unroll
        for (int j = 0; j < 4; j++)
            #pragma unroll
            for (int u = 0; u < 4; u++) acc[i][j][u] = 0.f;

    auto issue = [&](int s) {
        const int k0 = s * 64;
        const uint32_t st = sbase + (uint32_t)((s % NSTAGE) * STAGE64H) * 2;
        #pragma unroll
        for (int j = 0; j < 4; j++) {
            const int c = tid + 256 * j;
            const int r = c >> 3, kg = c & 7;
            const uint32_t off = (uint32_t)(r * LDT64 + kg * 8) * 2;
            cp16(st + off,                A0  + (size_t)(row0 + r) * E_ + k0 + kg * 8);
            cp16(st + TILE64H * 2 + off,  Btb + (size_t)(col0 + r) * E_ + k0 + kg * 8);
        }
        CP_COMMIT();
    };

    issue(0);
    issue(1);

    const int r   = lane & 7;
    const int sel = lane >> 3;

    for (int i = 0; i < 8; i++) {
        CP_WAIT(1);
        __syncthreads();

        if (i + 2 < 8) issue(i + 2);

        const uint32_t st = sbase + (uint32_t)((i % NSTAGE) * STAGE64H) * 2;
        const uint32_t a_base = st;
        const uint32_t b_base = st + TILE64H * 2;

        #pragma unroll
        for (int ks = 0; ks < 4; ks++) {
            const int k = ks * 16;
            uint32_t bfr[4][2];
            #pragma unroll
            for (int p = 0; p < 2; p++) {
                uint32_t addr = b_base +
                    (uint32_t)((wn * 32 + p * 16 + r + (sel >> 1) * 8) * LDT64 + k + (sel & 1) * 8) * 2;
                ldm_x4(bfr[2 * p][0], bfr[2 * p][1], bfr[2 * p + 1][0], bfr[2 * p + 1][1], addr);
            }
            const uint32_t a_off = a_base +
                (uint32_t)((wm * 64 + r + (sel & 1) * 8) * LDT64 + k + (sel >> 1) * 8) * 2;
            #pragma unroll
            for (int mt = 0; mt < 4; mt++) {
                uint32_t af[4];
                ldm_x4(af[0], af[1], af[2], af[3], a_off + (uint32_t)(mt * 16 * LDT64) * 2);
                #pragma unroll
                for (int nt = 0; nt < 4; nt++)
                    mma16816(acc[mt][nt], af, bfr[nt]);
            }
        }
    }

    #pragma unroll
    for (int mt = 0; mt < 4; mt++) {
        const int mg = row0 + wm * 64 + mt * 16 + (lane >> 2);
        #pragma unroll
        for (int nt = 0; nt < 4; nt++) {
            const int ng = col0 + wn * 32 + nt * 8 + (lane & 3) * 2;
            const float bi0 = bias_b[ng], bi1 = bias_b[ng + 1];
            *reinterpret_cast<float2*>(C + (size_t)mg * E_ + ng) =
                make_float2(acc[mt][nt][0] + bi0, acc[mt][nt][1] + bi1);
            *reinterpret_cast<float2*>(C + (size_t)(mg + 8) * E_ + ng) =
                make_float2(acc[mt][nt][2] + bi0, acc[mt][nt][3] + bi1);
        }
    }
}

// ---------------------------------------------------------------------------
// buildM HMMA: mt[m=b*512+n][e1] = fp16( sum_e2 wakt[m][e2]*wqh[e1][e2] + Wq[e1][n] )
// ---------------------------------------------------------------------------
__global__ __launch_bounds__(256, 2)
void hmma_buildM(const __half* __restrict__ A0, const __half* __restrict__ Bt,
                 const float* __restrict__ Wq, __half* __restrict__ Cmt)
{
    __shared__ __align__(16) __half As[2][128 * LDT];
    __shared__ __align__(16) __half Bs[2][128 * LDT];

    const int tid  = threadIdx.x;
    const int wid  = tid >> 5;
    const int lane = tid & 31;
    const int wm   = wid & 1;
    const int wn   = wid >> 1;
    const int row0 = blockIdx.y * 128;
    const int col0 = blockIdx.x * 128;

    const int lrow  = tid & 127;
    const int lhalf = tid >> 7;

    float acc[4][4][4];
    #pragma unroll
    for (int i = 0; i < 4; i++)
        #pragma unroll
        for (int j = 0; j < 4; j++)
            #pragma unroll
            for (int u = 0; u < 4; u++) acc[i][j][u] = 0.f;

    uint4 ar0, ar1, br0, br1;
    {
        const __half* ga = A0 + (size_t)(row0 + lrow) * E_ + lhalf * 16;
        const __half* gb = Bt + (size_t)(col0 + lrow) * E_ + lhalf * 16;
        ar0 = reinterpret_cast<const uint4*>(ga)[0];
        ar1 = reinterpret_cast<const uint4*>(ga)[1];
        br0 = reinterpret_cast<const uint4*>(gb)[0];
        br1 = reinterpret_cast<const uint4*>(gb)[1];
        __half* sa = &As[0][lrow * LDT + lhalf * 16];
        __half* sb = &Bs[0][lrow * LDT + lhalf * 16];
        reinterpret_cast<uint4*>(sa)[0] = ar0;
        reinterpret_cast<uint4*>(sa)[1] = ar1;
        reinterpret_cast<uint4*>(sb)[0] = br0;
        reinterpret_cast<uint4*>(sb)[1] = br1;
    }
    __syncthreads();

    const int r   = lane & 7;
    const int sel = lane >> 3;

    for (int i = 0; i < 16; i++) {
        const int buf = i & 1;
        if (i + 1 < 16) {
            const int k0 = (i + 1) * 32;
            const __half* ga = A0 + (size_t)(row0 + lrow) * E_ + k0 + lhalf * 16;
            const __half* gb = Bt + (size_t)(col0 + lrow) * E_ + k0 + lhalf * 16;
            ar0 = reinterpret_cast<const uint4*>(ga)[0];
            ar1 = reinterpret_cast<const uint4*>(ga)[1];
            br0 = reinterpret_cast<const uint4*>(gb)[0];
            br1 = reinterpret_cast<const uint4*>(gb)[1];
        }

        const uint32_t abase = smem_u32(&As[buf][0]);
        const uint32_t bbase = smem_u32(&Bs[buf][0]);
        #pragma unroll
        for (int ks = 0; ks < 2; ks++) {
            const int k = ks * 16;
            uint32_t bfr[4][2];
            #pragma unroll
            for (int p = 0; p < 2; p++) {
                uint32_t addr = bbase +
                    (uint32_t)((wn * 32 + p * 16 + r + (sel >> 1) * 8) * LDT + k + (sel & 1) * 8) * 2;
                ldm_x4(bfr[2 * p][0], bfr[2 * p][1], bfr[2 * p + 1][0], bfr[2 * p + 1][1], addr);
            }
            #pragma unroll
            for (int mt = 0; mt < 4; mt++) {
                uint32_t af[4];
                uint32_t addr = abase +
                    (uint32_t)((wm * 64 + mt * 16 + r + (sel & 1) * 8) * LDT + k + (sel >> 1) * 8) * 2;
                ldm_x4(af[0], af[1], af[2], af[3], addr);
                #pragma unroll
                for (int nt = 0; nt < 4; nt++)
                    mma16816(acc[mt][nt], af, bfr[nt]);
            }
        }

        if (i + 1 < 16) {
            const int nb = (i + 1) & 1;
            __half* sa = &As[nb][lrow * LDT + lhalf * 16];
            __half* sb = &Bs[nb][lrow * LDT + lhalf * 16];
            reinterpret_cast<uint4*>(sa)[0] = ar0;
            reinterpret_cast<uint4*>(sa)[1] = ar1;
            reinterpret_cast<uint4*>(sb)[0] = br0;
            reinterpret_cast<uint4*>(sb)[1] = br1;
            __syncthreads();
        }
    }

    #pragma unroll
    for (int mt = 0; mt < 4; mt++) {
        const int mg = row0 + wm * 64 + mt * 16 + (lane >> 2);
        const int n  = mg & 511;
        #pragma unroll
        for (int nt = 0; nt < 4; nt++) {
            const int ng = col0 + wn * 32 + nt * 8 + (lane & 3) * 2;
            float v0 = acc[mt][nt][0] + Wq[(size_t)ng * E_ + n];
            float v1 = acc[mt][nt][1] + Wq[(size_t)(ng + 1) * E_ + n];
            float v2 = acc[mt][nt][2] + Wq[(size_t)ng * E_ + n + 8];
            float v3 = acc[mt][nt][3] + Wq[(size_t)(ng + 1) * E_ + n + 8];
            *reinterpret_cast<__half2*>(Cmt + (size_t)mg * E_ + ng) =
                __half2(__float2half(v0), __float2half(v1));
            *reinterpret_cast<__half2*>(Cmt + (size_t)(mg + 8) * E_ + ng) =
                __half2(__float2half(v2), __float2half(v3));
        }
    }
}

// ---------------------------------------------------------------------------
// Fused: wakt = fp16(Wo^T * kf) (y<16); cb bias (y==16)
// ---------------------------------------------------------------------------
__global__ __launch_bounds__(256)
void woTkf_cbias_kernel(const float* __restrict__ Wo, const float* __restrict__ kf,
                        const float* __restrict__ bq, const float* __restrict__ bo,
                        __half* __restrict__ wakt, float* __restrict__ cb)
{
    const int b = blockIdx.z;
    if (blockIdx.y == 16) {
        if (blockIdx.x >= 2) return;
        const int n = blockIdx.x * 256 + threadIdx.x;
        float a = 0.f;
        for (int e = 0; e < E_; e++)
            a = fmaf(bq[e] * kf[b * E_ + e], Wo[(size_t)e * E_ + n], a);
        cb[b * E_ + n] = a + bo[n] + bq[n];
        return;
    }
    __shared__ float t[32][33];
    const int n0 = blockIdx.x * 32, e20 = blockIdx.y * 32;
    const int tx = threadIdx.x & 31, ty = threadIdx.x >> 5;
    #pragma unroll
    for (int j = 0; j < 4; j++) {
        const int e2 = e20 + ty * 4 + j;
        t[ty * 4 + j][tx] = Wo[(size_t)e2 * E_ + n0 + tx] * kf[b * E_ + e2];
    }
    __syncthreads();
    #pragma unroll
    for (int j = 0; j < 4; j++) {
        const int n = n0 + ty * 4 + j;
        wakt[((size_t)b * E_ + n) * E_ + e20 + tx] = __float2half(t[tx][ty * 4 + j]);
    }
}

// ---------------------------------------------------------------------------
// Fused: Cq = Wq@Waq (blocks 0..15); wqh = fp16(Wq) (blocks 16..271)
// ---------------------------------------------------------------------------
__global__ __launch_bounds__(256)
void prep_q_kernel(const float* __restrict__ Wq, const float* __restrict__ Wa,
                   const float* __restrict__ bvec, const float* __restrict__ ba,
                   float* __restrict__ C, float* __restrict__ cv,
                   __half* __restrict__ wqh)
{
    const int tid = threadIdx.x;
    if (blockIdx.x >= 16) {
        const int i = (blockIdx.x - 16) * 256 + tid;
        const float4 v = reinterpret_cast<const float4*>(Wq)[i];
        __half2* hp = reinterpret_cast<__half2*>(wqh) + 2 * i;
        hp[0] = __half2(__float2half(v.x), __float2half(v.y));
        hp[1] = __half2(__float2half(v.z), __float2half(v.w));
        return;
    }
    __shared__ float s[E_][H_];
    for (int i = tid; i < E_ * H_; i += 256) s[i >> 3][i & 7] = Wa[i];
    __syncthreads();
    const int e1 = blockIdx.x * 32 + (tid >> 3);
    const int h  = tid & 7;
    const float* wr = Wq + (size_t)e1 * E_;
    float acc = 0.f;
    for (int e2 = 0; e2 < E_; e2++) acc = fmaf(wr[e2], s[e2][h], acc);
    C[(size_t)e1 * H_ + h] = acc;
    if (blockIdx.x == 0 && tid < H_) {
        float a = 0.f;
        for (int e2 = 0; e2 < E_; e2++) a = fmaf(bvec[e2], s[e2][tid], a);
        cv[tid] = a + ba[tid];
    }
}

// ---------------------------------------------------------------------------
// C[bb][e1][h] = sum_e2 W[e1,e2] * scale[bb,e2] * Wa[e2,h]   (k path)
// ---------------------------------------------------------------------------
__global__ __launch_bounds__(256)
void cmat_kernel(const float* __restrict__ W, const float* __restrict__ Wa,
                 const float* __restrict__ bvec, const float* __restrict__ ba,
                 const float* __restrict__ scale,
                 float* __restrict__ C, float* __restrict__ cv)
{
    const int bb = blockIdx.y;
    __shared__ float s[E_][H_];
    const int tid = threadIdx.x;
    for (int i = tid; i < E_ * H_; i += 256) {
        const int e2 = i >> 3, h = i & 7;
        s[e2][h] = scale[bb * E_ + e2] * Wa[i];
    }
    __syncthreads();
    const int e1 = blockIdx.x * 32 + (tid >> 3);
    const int h  = tid & 7;
    const float* wr = W + (size_t)e1 * E_;
    float acc = 0.f;
    for (int e2 = 0; e2 < E_; e2++) acc = fmaf(wr[e2], s[e2][h], acc);
    C[((size_t)bb * E_ + e1) * H_ + h] = acc;
    if (blockIdx.x == 0 && tid < H_) {
        float a = 0.f;
        for (int e2 = 0; e2 < E_; e2++) a = fmaf(bvec[e2], s[e2][tid], a);
        cv[bb * H_ + tid] = a + ba[tid];
    }
}

// ---------------------------------------------------------------------------
// Fused: convert x -> fp16 AND q_scores = x@Cq + cq.
// All 4 row loads hoisted ahead of compute (MLP 4).
// ---------------------------------------------------------------------------
__global__ __launch_bounds__(256)
void split_scores_kernel(const float* __restrict__ x, __half* __restrict__ ah,
                         const float* __restrict__ Cq, const float* __restrict__ cq,
                         float* __restrict__ S)
{
    __shared__ float wT[H_][E_];
    __shared__ float bsh[H_];
    const int tid = threadIdx.x;
    for (int i = tid; i < E_ * H_; i += 256) wT[i & 7][i >> 3] = Cq[i];
    if (tid < H_) bsh[tid] = cq[tid];
    __syncthreads();

    const int warp = tid >> 5, lane = tid & 31;
    const int m = blockIdx.x * 8 + warp;
    const float4* xr = reinterpret_cast<const float4*>(x + (size_t)m * E_);

    // hoisted loads: 4 outstanding LDG.128 before any dependent use
    float4 v[4];
    #pragma unroll
    for (int c = 0; c < 4; c++) v[c] = xr[c * 32 + lane];

    float s[H_] = {0.f, 0.f, 0.f, 0.f, 0.f, 0.f, 0.f, 0.f};
    #pragma unroll
    for (int c = 0; c < 4; c++) {
        const int e = (c * 32 + lane) * 4;
        #pragma unroll
        for (int h = 0; h < H_; h++)
            s[h] += v[c].x * wT[h][e] + v[c].y * wT[h][e + 1]
                  + v[c].z * wT[h][e + 2] + v[c].w * wT[h][e + 3];
        const __half2 p0 = __half2(__float2half(v[c].x), __float2half(v[c].y));
        const __half2 p1 = __half2(__float2half(v[c].z), __float2half(v[c].w));
        uint2 st;
        st.x = *reinterpret_cast<const uint32_t*>(&p0);
        st.y = *reinterpret_cast<const uint32_t*>(&p1);
        *reinterpret_cast<uint2*>(ah + (size_t)m * E_ + e) = st;
    }
    #pragma unroll
    for (int off = 16; off; off >>= 1)
        #pragma unroll
        for (int h = 0; h < H_; h++) s[h] += __shfl_xor_sync(0xffffffffu, s[h], off);
    if (lane < H_) S[(size_t)m * H_ + lane] = s[lane] + bsh[lane];
}

// k_scores with per-batch C, reading fp16 x; both loads hoisted.
__global__ __launch_bounds__(256)
void scores_pb_kernel(const __half* __restrict__ xh, const float* __restrict__ C,
                      const float* __restrict__ cv, float* __restrict__ S)
{
    const int b = blockIdx.x >> 9;
    __shared__ float wT[H_][E_];
    __shared__ float bsh[H_];
    const int tid = threadIdx.x;
    const float* Cb = C + (size_t)b * E_ * H_;
    for (int i = tid; i < E_ * H_; i += 256) wT[i & 7][i >> 3] = Cb[i];
    if (tid < H_) bsh[tid] = cv[b * H_ + tid];
    __syncthreads();

    const int warp = tid >> 5, lane = tid & 31;
    const int m = blockIdx.x * 8 + warp;
    const uint4* xr = reinterpret_cast<const uint4*>(xh + (size_t)m * E_);

    uint4 raw[2];
    raw[0] = xr[lane];
    raw[1] = xr[32 + lane];

    float s[H_] = {0.f, 0.f, 0.f, 0.f, 0.f, 0.f, 0.f, 0.f};
    #pragma unroll
    for (int c = 0; c < 2; c++) {
        const int e = (c * 32 + lane) * 8;
        const __half2* p = reinterpret_cast<const __half2*>(&raw[c]);
        #pragma unroll
        for (int j = 0; j < 4; j++) {
            const float2 f = __half22float2(p[j]);
            #pragma unroll
            for (int h = 0; h < H_; h++)
                s[h] += f.x * wT[h][e + 2 * j] + f.y * wT[h][e + 2 * j + 1];
        }
    }
    #pragma unroll
    for (int off = 16; off; off >>= 1)
        #pragma unroll
        for (int h = 0; h < H_; h++) s[h] += __shfl_xor_sync(0xffffffffu, s[h], off);
    if (lane < H_) S[(size_t)m * H_ + lane] = s[lane] + bsh[lane];
}

// ---------------------------------------------------------------------------
// softmax weights per (b,h) — 1024 threads
// ---------------------------------------------------------------------------
__global__ __launch_bounds__(1024)
void softmax_kernel(const float* __restrict__ S, const unsigned char* __restrict__ mask,
                    float* __restrict__ w)
{
    const int bh = blockIdx.x;
    const int b = bh >> 3, h = bh & 7;
    __shared__ float buf[T_];
    __shared__ float red[1024];
    const int tid = threadIdx.x;

    float mx = -INFINITY;
    #pragma unroll
    for (int c = 0; c < 4; c++) {
        const int t = c * 1024 + tid;
        float s = S[((size_t)b * T_ + t) * H_ + h] * 0.125f;
        if (mask[b * T_ + t]) s = -INFINITY;
        buf[t] = s;
        mx = fmaxf(mx, s);
    }
    red[tid] = mx; __syncthreads();
    #pragma unroll
    for (int s2 = 512; s2 > 0; s2 >>= 1) {
        if (tid < s2) red[tid] = fmaxf(red[tid], red[tid + s2]);
        __syncthreads();
    }
    mx = red[0];
    __syncthreads();

    float sum = 0.f;
    #pragma unroll
    for (int c = 0; c < 4; c++) {
        const int t = c * 1024 + tid;
        const float e = expf(buf[t] - mx);
        buf[t] = e;
        sum += e;
    }
    red[tid] = sum; __syncthreads();
    #pragma unroll
    for (int s2 = 512; s2 > 0; s2 >>= 1) {
        if (tid < s2) red[tid] += red[tid + s2];
        __syncthreads();
    }
    const float inv = 1.f / red[0];
    __syncthreads();
    #pragma unroll
    for (int c = 0; c < 4; c++) {
        const int t = c * 1024 + tid;
        w[(size_t)bh * T_ + t] = buf[t] * inv;
    }
}

// ---------------------------------------------------------------------------
// pool fp16 x with all 8 head-weights (R12 version): partial[chunk][b][h][e],
// 64 t per chunk. grid (NCHUNK, B), 256 threads.
// ---------------------------------------------------------------------------
__global__ __launch_bounds__(256)
void pool_x_kernel(const float* __restrict__ w, const __half* __restrict__ xh,
                   float* __restrict__ partial)
{
    const int chunk = blockIdx.x, b = blockIdx.y;
    __shared__ float ws[H_][64];
    const int tid = threadIdx.x;
    for (int i = tid; i < H_ * 64; i += 256)
        ws[i >> 6][i & 63] = w[(size_t)(b * 8 + (i >> 6)) * T_ + chunk * 64 + (i & 63)];
    __syncthreads();

    float acc[H_][2];
    #pragma unroll
    for (int h = 0; h < H_; h++) { acc[h][0] = 0.f; acc[h][1] = 0.f; }

    const __half* xp = xh + (size_t)b * T_ * E_ + (size_t)chunk * 64 * E_;
    for (int tt = 0; tt < 64; tt++) {
        const __half2 hv = *reinterpret_cast<const __half2*>(xp + (size_t)tt * E_ + tid * 2);
        const float2 v = __half22float2(hv);
        #pragma unroll
        for (int h = 0; h < H_; h++) {
            acc[h][0] = fmaf(ws[h][tt], v.x, acc[h][0]);
            acc[h][1] = fmaf(ws[h][tt], v.y, acc[h][1]);
        }
    }
    #pragma unroll
    for (int h = 0; h < H_; h++) {
        float* pp = partial + (((size_t)chunk * 8 + b) * 8 + h) * E_ + tid * 2;
        pp[0] = acc[h][0]; pp[1] = acc[h][1];
    }
}

// ---------------------------------------------------------------------------
// flat: out[b, h*64+d] = (sum_c partial[c][b][h][:]) @ W[:, h*64+d] + bvec  (*qf)
// ---------------------------------------------------------------------------
template<bool MULQF>
__global__ __launch_bounds__(256)
void flat_kernel(const float* __restrict__ partial, const float* __restrict__ W,
                 const float* __restrict__ bvec, const float* __restrict__ qf_in,
                 float* __restrict__ out)
{
    const int b = blockIdx.x, h = blockIdx.y;
    __shared__ float px[E_];
    __shared__ float red[256];
    const int tid = threadIdx.x;
    for (int e = tid; e < E_; e += 256) {
        float a = 0.f;
        #pragma unroll
        for (int c = 0; c < NCHUNK; c++) a += partial[(((size_t)c * 8 + b) * 8 + h) * E_ + e];
        px[e] = a;
    }
    __syncthreads();
    const int d = tid & 63, q = tid >> 6;
    float acc = 0.f;
    for (int k = q * 128; k < q * 128 + 128; k++)
        acc = fmaf(px[k], W[(size_t)k * E_ + h * D_ + d], acc);
    red[tid] = acc; __syncthreads();
    if (tid < 64) {
        float v = red[tid] + red[tid + 64] + red[tid + 128] + red[tid + 192] + bvec[h * D_ + d];
        if (MULQF) v *= qf_in[b * E_ + h * D_ + d];
        out[b * E_ + h * D_ + d] = v;
    }
}

// ---------------------------------------------------------------------------
// Launch sequence
// ---------------------------------------------------------------------------
extern "C" void kernel_launch(void* const* d_in, const int* in_sizes, int n_in,
                              void* d_out, int out_size)
{
    const float* x            = (const float*)d_in[0];
    const unsigned char* mask = (const unsigned char*)d_in[3];
    const float* Wq  = (const float*)d_in[4];
    const float* bq  = (const float*)d_in[5];
    const float* Waq = (const float*)d_in[6];
    const float* baq = (const float*)d_in[7];
    const float* Wk  = (const float*)d_in[8];
    const float* bk  = (const float*)d_in[9];
    const float* Wak = (const float*)d_in[10];
    const float* bak = (const float*)d_in[11];
    const float* Wo  = (const float*)d_in[12];
    const float* bo  = (const float*)d_in[13];
    float* out = (float*)d_out;

    float *sc_, *w_, *pp_, *qf_, *kf_, *Cq_, *cq_, *Ck_, *ck_, *cb_;
    __half *ah, *mt, *wakt, *wqh;
    cudaGetSymbolAddress((void**)&sc_, g_scores);
    cudaGetSymbolAddress((void**)&w_,  g_w);
    cudaGetSymbolAddress((void**)&pp_, g_partial);
    cudaGetSymbolAddress((void**)&qf_, g_qf);
    cudaGetSymbolAddress((void**)&kf_, g_kf);
    cudaGetSymbolAddress((void**)&Cq_, g_Cq);
    cudaGetSymbolAddress((void**)&cq_, g_cq);
    cudaGetSymbolAddress((void**)&Ck_, g_Ck);
    cudaGetSymbolAddress((void**)&ck_, g_ck);
    cudaGetSymbolAddress((void**)&cb_, g_cb);
    cudaGetSymbolAddress((void**)&ah,  g_ah);
    cudaGetSymbolAddress((void**)&mt,  g_mt);
    cudaGetSymbolAddress((void**)&wakt, g_wakt);
    cudaGetSymbolAddress((void**)&wqh, g_wqh);

    cudaFuncSetAttribute(hmma_gemm_fused, cudaFuncAttributeMaxDynamicSharedMemorySize, GEMM_SMEM);

    // 1) Cq = Wq@Waq + wqh convert (fused); fp16 convert of x + q_scores (fused)
    prep_q_kernel<<<16 + 256, 256>>>(Wq, Waq, bq, baq, Cq_, cq_, wqh);
    split_scores_kernel<<<M_ / 8, 256>>>(x, ah, Cq_, cq_, sc_);
    // 2) q softmax + pool (fp16 x) + q_flat
    softmax_kernel<<<B_ * H_, 1024>>>(sc_, mask, w_);
    pool_x_kernel<<<dim3(NCHUNK, B_), 256>>>(w_, ah, pp_);
    flat_kernel<false><<<dim3(B_, H_), 256>>>(pp_, Wq, bq, nullptr, qf_);
    // 3) per-batch Ck; k_scores from fp16 x
    cmat_kernel<<<dim3(16, B_), 256>>>(Wk, Wak, bk, bak, qf_, Ck_, ck_);
    scores_pb_kernel<<<M_ / 8, 256>>>(ah, Ck_, ck_, sc_);
    // 4) k softmax + pool (fp16 x) + k_flat
    softmax_kernel<<<B_ * H_, 1024>>>(sc_, mask, w_);
    pool_x_kernel<<<dim3(NCHUNK, B_), 256>>>(w_, ah, pp_);
    flat_kernel<true><<<dim3(B_, H_), 256>>>(pp_, Wk, bk, qf_, kf_);
    // 5) M^T via tensor cores (woTkf + cbias fused)
    woTkf_cbias_kernel<<<dim3(16, 17, B_), 256>>>(Wo, kf_, bq, bo, wakt, cb_);
    hmma_buildM<<<dim3(E_ / 128, B_ * E_ / 128), 256>>>(wakt, wqh, Wq, mt);
    // 6) final GEMM: out = x @ M_b + cb_b
    hmma_gemm_fused<<<dim3(E_ / 128, M_ / 128), 256, GEMM_SMEM>>>(ah, mt, cb_, out);
}